// round 2
// baseline (speedup 1.0000x reference)
#include <cuda_runtime.h>
#include <cuda_bf16.h>
#include <stdint.h>

#define NN 50000
#define EE 250000
#define DD 32

// Static scratch (no allocations allowed)
__device__ float g_h[NN * DD];      // node features
__device__ float g_uvr[NN * 96];    // per-node [u | v | r] = relu(h) @ [W1 | B1 | root]
__device__ float g_aggr[NN * DD];   // scatter accumulator
__device__ float g_cnt[NN];         // in-degree

// h0[n,d] = x[n] * node_W[d] + node_b[d]
__global__ void init_h_kernel(const float* __restrict__ x,
                              const float* __restrict__ nW,
                              const float* __restrict__ nb,
                              int n_total) {
    int idx = blockIdx.x * blockDim.x + threadIdx.x;
    if (idx >= n_total) return;
    int n = idx >> 5, d = idx & 31;
    g_h[idx] = fmaf(x[n], nW[d], nb[d]);
}

// in-degree (as float)
__global__ void degree_kernel(const int* __restrict__ ei, int E) {
    int e = blockIdx.x * blockDim.x + threadIdx.x;
    if (e >= E) return;
    int dst = ei[E + e];
    atomicAdd(&g_cnt[dst], 1.0f);
}

// uvr[n, 0:96] = relu(h[n]) @ [W1 | B1 | root]   (one warp per node)
__global__ void gemm_kernel(const float* __restrict__ l1W,
                            const float* __restrict__ l1b,
                            const float* __restrict__ root,
                            int N) {
    __shared__ float Ws[3 * 1024];
    int tid = threadIdx.x;
    for (int k = tid; k < 1024; k += blockDim.x) {
        Ws[k]        = l1W[k];
        Ws[1024 + k] = l1b[k];
        Ws[2048 + k] = root[k];
    }
    __syncthreads();
    int warp = tid >> 5, lane = tid & 31;
    int n = blockIdx.x * (blockDim.x >> 5) + warp;
    if (n >= N) return;
    float rv = fmaxf(g_h[n * 32 + lane], 0.0f);
    float au = 0.f, av = 0.f, ar = 0.f;
#pragma unroll
    for (int i = 0; i < 32; i++) {
        float b = __shfl_sync(0xffffffffu, rv, i);
        au = fmaf(b, Ws[i * 32 + lane], au);
        av = fmaf(b, Ws[1024 + i * 32 + lane], av);
        ar = fmaf(b, Ws[2048 + i * 32 + lane], ar);
    }
    float* o = &g_uvr[n * 96];
    o[lane]      = au;
    o[32 + lane] = av;
    o[64 + lane] = ar;
}

// per edge: aggr[dst] += ea[e]*u[src] + v[src]   (one warp per edge, one lane per channel)
__global__ void scatter_kernel(const int* __restrict__ ei,
                               const float* __restrict__ ea,
                               int E) {
    int idx = blockIdx.x * blockDim.x + threadIdx.x;
    int e = idx >> 5;
    int d = idx & 31;
    if (e >= E) return;
    int src = ei[e];
    int dst = ei[E + e];
    float a = ea[e];
    const float* o = &g_uvr[src * 96];
    float m = fmaf(a, o[d], o[32 + d]);
    atomicAdd(&g_aggr[dst * 32 + d], m);
}

// h_out = aggr / max(cnt,1) + r + conv_b ; optionally clear aggr for next layer
__global__ void combine_kernel(const float* __restrict__ convb,
                               float* __restrict__ hout,
                               int n_total, int clear_aggr) {
    int idx = blockIdx.x * blockDim.x + threadIdx.x;
    if (idx >= n_total) return;
    int n = idx >> 5, d = idx & 31;
    float c = fmaxf(g_cnt[n], 1.0f);
    float val = g_aggr[idx] / c + g_uvr[n * 96 + 64 + d] + convb[d];
    hout[idx] = val;
    if (clear_aggr) g_aggr[idx] = 0.0f;
}

extern "C" void kernel_launch(void* const* d_in, const int* in_sizes, int n_in,
                              void* d_out, int out_size) {
    const float* x     = (const float*)d_in[0];
    const int*   ei    = (const int*)d_in[1];   // int32 on the wire (jax x64 disabled)
    const float* ea    = (const float*)d_in[2];
    // d_in[3] = i (always 2 -> 3 layers), d_in[4] = dummy
    const float* nW    = (const float*)d_in[5];
    const float* nb    = (const float*)d_in[6];
    const float* l1W   = (const float*)d_in[7];
    const float* l1b   = (const float*)d_in[8];
    const float* root  = (const float*)d_in[9];
    const float* convb = (const float*)d_in[10];

    int N = in_sizes[0];          // 50000
    int E = in_sizes[2];          // 250000
    float* out = (float*)d_out;

    void* p_aggr = nullptr; void* p_cnt = nullptr; void* p_h = nullptr;
    cudaGetSymbolAddress(&p_aggr, g_aggr);
    cudaGetSymbolAddress(&p_cnt,  g_cnt);
    cudaGetSymbolAddress(&p_h,    g_h);
    float* hbuf = (float*)p_h;

    cudaMemsetAsync(p_aggr, 0, (size_t)N * DD * sizeof(float));
    cudaMemsetAsync(p_cnt,  0, (size_t)N * sizeof(float));

    int n_total = N * DD;
    int tb = 256;
    int blks_nd = (n_total + tb - 1) / tb;            // node*channel grids
    int blks_e  = (E + tb - 1) / tb;                  // per-edge grid
    int blks_ew = ((E * 32) + tb - 1) / tb;           // warp-per-edge grid
    int blks_g  = (N + (tb / 32) - 1) / (tb / 32);    // warp-per-node grid

    init_h_kernel<<<blks_nd, tb>>>(x, nW, nb, n_total);
    degree_kernel<<<blks_e, tb>>>(ei, E);

    // 3 layers (i = 2 -> min(i+1, 3) = 3)
    for (int layer = 0; layer < 3; layer++) {
        gemm_kernel<<<blks_g, tb>>>(l1W, l1b, root, N);
        scatter_kernel<<<blks_ew, tb>>>(ei, ea, E);
        int last = (layer == 2);
        combine_kernel<<<blks_nd, tb>>>(convb, last ? out : hbuf,
                                        n_total, last ? 0 : 1);
    }
}

// round 3
// speedup vs baseline: 1.3202x; 1.3202x over previous
#include <cuda_runtime.h>
#include <cuda_bf16.h>
#include <stdint.h>

#define NN 50000
#define EE 250000
#define DD 32
#define FULL 0xffffffffu

// Static scratch
__device__ int   g_cnt[NN];           // degree histogram
__device__ int   g_off[NN + 1];       // CSR offsets (exclusive)
__device__ int   g_cur[NN];           // insertion cursors
__device__ int   g_part[64];          // scan partials
__device__ int   g_csr_src[EE];
__device__ float g_csr_ea[EE];
__device__ float g_uvrA[NN * 96];     // [u | v | r] ping
__device__ float g_uvrB[NN * 96];     // [u | v | r] pong

// ---------------- CSR build ----------------
__global__ void hist_kernel(const int* __restrict__ ei, int E) {
    int e = blockIdx.x * blockDim.x + threadIdx.x;
    if (e >= E) return;
    atomicAdd(&g_cnt[ei[E + e]], 1);
}

__global__ void scan1_kernel(int N) {
    __shared__ int s[1024];
    int tid = threadIdx.x;
    int i = blockIdx.x * 1024 + tid;
    int v = (i < N) ? g_cnt[i] : 0;
    s[tid] = v;
    __syncthreads();
#pragma unroll
    for (int o = 1; o < 1024; o <<= 1) {
        int t = (tid >= o) ? s[tid - o] : 0;
        __syncthreads();
        s[tid] += t;
        __syncthreads();
    }
    if (i < N) g_off[i + 1] = s[tid];
    if (tid == 1023) g_part[blockIdx.x] = s[1023];
}

__global__ void scan2_kernel(int nb) {
    if (threadIdx.x == 0) {
        int run = 0;
        for (int b = 0; b < nb; b++) { int t = g_part[b]; g_part[b] = run; run += t; }
    }
}

__global__ void scan3_kernel(int N) {
    int i = blockIdx.x * 1024 + threadIdx.x;
    if (i == 0) g_off[0] = 0;
    if (i < N) {
        int v = g_off[i + 1] + g_part[blockIdx.x];
        g_off[i + 1] = v;
        g_cur[i] = v - g_cnt[i];   // exclusive offset
    }
}

__global__ void permute_kernel(const int* __restrict__ ei,
                               const float* __restrict__ ea, int E) {
    int e = blockIdx.x * blockDim.x + threadIdx.x;
    if (e >= E) return;
    int dst = ei[E + e];
    int p = atomicAdd(&g_cur[dst], 1);
    g_csr_src[p] = ei[e];
    g_csr_ea[p] = ea[e];
}

// ---------------- shuffle GEMM helper ----------------
__device__ __forceinline__ void shfl_gemm(float rv, const float* Ws, int lane,
                                          float* o) {
    float au = 0.f, av = 0.f, ar = 0.f;
#pragma unroll
    for (int i = 0; i < 32; i++) {
        float b = __shfl_sync(FULL, rv, i);
        au = fmaf(b, Ws[i * 32 + lane], au);
        av = fmaf(b, Ws[1024 + i * 32 + lane], av);
        ar = fmaf(b, Ws[2048 + i * 32 + lane], ar);
    }
    o[lane]      = au;
    o[32 + lane] = av;
    o[64 + lane] = ar;
}

__device__ __forceinline__ void load_weights(float* Ws,
                                             const float* __restrict__ l1W,
                                             const float* __restrict__ l1b,
                                             const float* __restrict__ root) {
    for (int k = threadIdx.x; k < 1024; k += blockDim.x) {
        Ws[k]        = l1W[k];
        Ws[1024 + k] = l1b[k];
        Ws[2048 + k] = root[k];
    }
    __syncthreads();
}

// gemm0: uvrA = relu(x*nW+nb) @ [W1|B1|root]
__global__ void gemm0_kernel(const float* __restrict__ x,
                             const float* __restrict__ nW,
                             const float* __restrict__ nb,
                             const float* __restrict__ l1W,
                             const float* __restrict__ l1b,
                             const float* __restrict__ root, int N) {
    __shared__ float Ws[3 * 1024];
    load_weights(Ws, l1W, l1b, root);
    int warp = threadIdx.x >> 5, lane = threadIdx.x & 31;
    int n = blockIdx.x * (blockDim.x >> 5) + warp;
    if (n >= N) return;
    float h = fmaf(x[n], nW[lane], nb[lane]);
    shfl_gemm(fmaxf(h, 0.f), Ws, lane, &g_uvrA[n * 96]);
}

// fused layer: gather mean -> combine -> (relu -> gemm | write out)
__global__ void layer_kernel(const float* __restrict__ uvr_in,
                             float* __restrict__ uvr_out,
                             const float* __restrict__ l1W,
                             const float* __restrict__ l1b,
                             const float* __restrict__ root,
                             const float* __restrict__ convb,
                             float* __restrict__ out,
                             int N, int final_layer) {
    __shared__ float Ws[3 * 1024];
    if (!final_layer) load_weights(Ws, l1W, l1b, root);
    int warp = threadIdx.x >> 5, lane = threadIdx.x & 31;
    int n = blockIdx.x * (blockDim.x >> 5) + warp;
    if (n >= N) return;

    int start = g_off[n], end = g_off[n + 1];
    float acc = 0.f;
    for (int base = start; base < end; base += 32) {
        int m = min(32, end - base);
        int s = 0; float a = 0.f;
        if (lane < m) { s = g_csr_src[base + lane]; a = g_csr_ea[base + lane]; }
        for (int j = 0; j < m; j++) {
            int   ss = __shfl_sync(FULL, s, j);
            float aa = __shfl_sync(FULL, a, j);
            const float* o = &uvr_in[ss * 96];
            acc = fmaf(aa, __ldg(&o[lane]), acc) + __ldg(&o[32 + lane]);
        }
    }
    float c = fmaxf((float)(end - start), 1.0f);
    float h = acc / c + uvr_in[n * 96 + 64 + lane] + convb[lane];

    if (final_layer) { out[n * 32 + lane] = h; return; }
    shfl_gemm(fmaxf(h, 0.f), Ws, lane, &uvr_out[n * 96]);
}

extern "C" void kernel_launch(void* const* d_in, const int* in_sizes, int n_in,
                              void* d_out, int out_size) {
    const float* x     = (const float*)d_in[0];
    const int*   ei    = (const int*)d_in[1];
    const float* ea    = (const float*)d_in[2];
    const float* nW    = (const float*)d_in[5];
    const float* nb    = (const float*)d_in[6];
    const float* l1W   = (const float*)d_in[7];
    const float* l1b   = (const float*)d_in[8];
    const float* root  = (const float*)d_in[9];
    const float* convb = (const float*)d_in[10];

    int N = in_sizes[0];      // 50000
    int E = in_sizes[2];      // 250000
    float* out = (float*)d_out;

    void* p_cnt = nullptr; void* p_A = nullptr; void* p_B = nullptr;
    cudaGetSymbolAddress(&p_cnt, g_cnt);
    cudaGetSymbolAddress(&p_A, g_uvrA);
    cudaGetSymbolAddress(&p_B, g_uvrB);
    float* A = (float*)p_A;
    float* B = (float*)p_B;

    cudaMemsetAsync(p_cnt, 0, (size_t)N * sizeof(int));

    int tb = 256;
    int blks_e = (E + tb - 1) / tb;
    int nb1 = (N + 1023) / 1024;
    int blks_w = (N + (tb / 32) - 1) / (tb / 32);   // warp-per-node

    // CSR build
    hist_kernel<<<blks_e, tb>>>(ei, E);
    scan1_kernel<<<nb1, 1024>>>(N);
    scan2_kernel<<<1, 32>>>(nb1);
    scan3_kernel<<<nb1, 1024>>>(N);
    permute_kernel<<<blks_e, tb>>>(ei, ea, E);

    // layer pipeline (i = 2 -> 3 layers)
    gemm0_kernel<<<blks_w, tb>>>(x, nW, nb, l1W, l1b, root, N);
    layer_kernel<<<blks_w, tb>>>(A, B, l1W, l1b, root, convb, out, N, 0);
    layer_kernel<<<blks_w, tb>>>(B, A, l1W, l1b, root, convb, out, N, 0);
    layer_kernel<<<blks_w, tb>>>(A, B, l1W, l1b, root, convb, out, N, 1);
}